// round 6
// baseline (speedup 1.0000x reference)
#include <cuda_runtime.h>
#include <math.h>

#define TMAX 256
#define LOG2PI 1.8378770664093453

// ---------------- device scratch ----------------
__device__ float g_P[TMAX][256];
__device__ float g_ba[TMAX][16];
__device__ float g_Lr[TMAX][256];
__device__ float g_Lu[TMAX][16];
__device__ float g_Sr[32][256];
__device__ float g_Su[32][16];
__device__ float g_Gr[32][256];
__device__ float g_Gu[32][16];
__device__ float g_OmP[256], g_om[256], g_Om0[256];
__device__ float g_fcF[256], g_fmF[16];
__device__ double g_part[65];

#define BARA() asm volatile("bar.sync 1, 128;" ::: "memory")
#define BARB() asm volatile("bar.sync 2, 128;" ::: "memory")
#define BAR0() asm volatile("bar.sync 0, 256;" ::: "memory")
#define BAR3() asm volatile("bar.sync 3, 96;" ::: "memory")
#define BAR4() asm volatile("bar.sync 4, 96;" ::: "memory")

// ---------------- dot helpers ----------------
__device__ __forceinline__ float dot_rc(const float* A, const float* B, int i, int j) {
    float s = 0.f;
#pragma unroll
    for (int k = 0; k < 16; k++) s = fmaf(A[i * 16 + k], B[k * 16 + j], s);
    return s;
}
__device__ __forceinline__ float dot_tc(const float* A, const float* B, int i, int j) { // A^T B
    float s = 0.f;
#pragma unroll
    for (int k = 0; k < 16; k++) s = fmaf(A[k * 16 + i], B[k * 16 + j], s);
    return s;
}
__device__ __forceinline__ float dot_rt(const float* A, const float* B, int i, int j) { // A B^T
    float s = 0.f;
#pragma unroll
    for (int k = 0; k < 16; k++) s = fmaf(A[i * 16 + k], B[j * 16 + k], s);
    return s;
}
__device__ __forceinline__ float dot_rowreg_col(const float* row, const float* B, int j) {
    float s = 0.f;
#pragma unroll
    for (int k = 0; k < 16; k++) s = fmaf(row[k], B[k * 16 + j], s);
    return s;
}
__device__ __forceinline__ float mv(const float* M, const float* v, int r) {
    float s = 0.f;
#pragma unroll
    for (int k = 0; k < 16; k++) s = fmaf(M[r * 16 + k], v[k], s);
    return s;
}

// Single-warp register-resident Gauss-Jordan solve: A (16x16 SPD) X = B.
// Writes X^T (row-major) to Xt. Returns logdet(A) on all lanes.
__device__ __forceinline__ float warp_gj_solve(const float* Am, const float* Bm,
                                               float* Xt, int lane) {
    float a[16];
    {
        const float* src = (lane < 16) ? (Am + lane) : (Bm + lane - 16);
#pragma unroll
        for (int r = 0; r < 16; r++) a[r] = src[r * 16];
    }
    float mypiv = 1.f;
#pragma unroll
    for (int p = 0; p < 16; p++) {
        float f[16];
#pragma unroll
        for (int r = 0; r < 16; r++) f[r] = __shfl_sync(0xffffffffu, a[r], p);
        float x = f[p];
        if (lane == p) mypiv = x;
        float r0;
        asm("rcp.approx.f32 %0, %1;" : "=f"(r0) : "f"(x));
        float pivinv = r0 * (2.0f - x * r0);
        a[p] *= pivinv;
#pragma unroll
        for (int r = 0; r < 16; r++)
            if (r != p) a[r] = fmaf(-f[r], a[p], a[r]);
    }
    float lg = __logf(mypiv);
#pragma unroll
    for (int o = 16; o; o >>= 1) lg += __shfl_xor_sync(0xffffffffu, lg, o);
    if (lane >= 16) {
        float4* dst = reinterpret_cast<float4*>(Xt + (lane - 16) * 16);
        dst[0] = make_float4(a[0], a[1], a[2], a[3]);
        dst[1] = make_float4(a[4], a[5], a[6], a[7]);
        dst[2] = make_float4(a[8], a[9], a[10], a[11]);
        dst[3] = make_float4(a[12], a[13], a[14], a[15]);
    }
    return lg;
}

// ---------------- forward kernel ----------------
struct SMF {
    float Wq[256], Sq[256], Hq[256], Rq[256], Wp[256], Wep[256];
    float WH[256], C1[256], C2[256];
    float Om_p[256], om[256], Om0[256], Em[256], Fm[256];
    float fcb[2][256], M[2][256], pc[2][256], Hpc[2][256], S[256], K[256];
    float WqPC[256], WHPC[256], Pqq[256], Phh[256], Phq[256], HW[256], HH[256];
    float WqK[256], WHK[256];
    float bA[2][256], t1[256], t2[256], t3[256], OmpA[256], G[256], Go[256], bcov[256];
    float bq[16], dq[16], bp[16], ebp[16], ppm[16], cq2[16];
    float fmb[2][16], pm[2][16], innov[16], y[16];
    double dred[8], dsc[2];
};

__global__ void __launch_bounds__(256, 1) lgq_fwd(
    const float* obs, const float* p_prior_mean, const float* p_prior_cov,
    const float* p_trans_w, const float* p_trans_b, const float* p_trans_cov,
    const float* p_emis_w, const float* p_emis_b, const float* p_emis_cov,
    const float* q_prior_mean, const float* q_prior_cov, const float* q_trans_w,
    const float* q_trans_b, const float* q_trans_cov, const float* q_emis_w,
    const float* q_emis_b, const float* q_emis_cov, int Tn) {
    __shared__ SMF s;
    const int tid = threadIdx.x;
    const int i = tid >> 4, j = tid & 15;
    const int lane = tid & 31, wid = tid >> 5;

    // load constants
    s.Wq[tid] = q_trans_w[tid];
    s.Sq[tid] = q_trans_cov[tid];
    s.Hq[tid] = q_emis_w[tid];
    s.Rq[tid] = q_emis_cov[tid];
    s.Wp[tid] = p_trans_w[tid];
    s.Wep[tid] = p_emis_w[tid];
    if (tid < 16) {
        s.bq[tid] = q_trans_b[tid];
        s.dq[tid] = q_emis_b[tid];
        s.bp[tid] = p_trans_b[tid];
        s.ebp[tid] = p_emis_b[tid];
        s.ppm[tid] = p_prior_mean[tid];
    }
    __syncthreads();

    // derived constants
    s.WH[tid] = dot_rc(s.Hq, s.Wq, i, j);
    s.C1[tid] = dot_rc(s.Hq, s.Sq, i, j);
    if (tid < 16) s.cq2[tid] = mv(s.Hq, s.bq, tid) + s.dq[tid];

    // ---- setup: constant inverses / logdets ----
    float LDp = 0.f, LDe = 0.f, LDpr = 0.f, LDSq = 0.f, LDRq = 0.f, ldqp = 0.f, ldS0 = 0.f;
    s.t2[tid] = (i == j) ? 1.f : 0.f;  // identity RHS
    s.S[tid] = p_trans_cov[tid];
    __syncthreads();
    s.C2[tid] = dot_rt(s.C1, s.Hq, i, j) + s.Rq[tid];
    if (wid == 0) LDp = warp_gj_solve(s.S, s.t2, s.K, lane);
    __syncthreads();
    s.Om_p[tid] = -0.5f * s.K[tid];
    s.t3[tid] = dot_rc(s.K, s.Wp, i, j);
    __syncthreads();
    s.Fm[tid] = dot_tc(s.Wp, s.t3, i, j);
    s.S[tid] = p_emis_cov[tid];
    __syncthreads();
    if (wid == 0) LDe = warp_gj_solve(s.S, s.t2, s.K, lane);
    __syncthreads();
    s.om[tid] = -0.5f * s.K[tid];
    s.S[tid] = p_prior_cov[tid];
    __syncthreads();
    s.t3[tid] = dot_rc(s.om, s.Wep, i, j);
    if (wid == 0) LDpr = warp_gj_solve(s.S, s.t2, s.K, lane);
    __syncthreads();
    s.Em[tid] = dot_tc(s.Wep, s.t3, i, j);
    s.Om0[tid] = -0.5f * s.K[tid];
    s.S[tid] = q_trans_cov[tid];
    __syncthreads();
    if (wid == 0) LDSq = warp_gj_solve(s.S, s.t2, s.t3, lane);
    __syncthreads();
    s.S[tid] = q_emis_cov[tid];
    __syncthreads();
    if (wid == 0) LDRq = warp_gj_solve(s.S, s.t2, s.t3, lane);
    __syncthreads();

    // ---- t=0 Kalman update ----
    s.pc[0][tid] = q_prior_cov[tid];
    if (tid < 16) {
        s.pm[0][tid] = q_prior_mean[tid];
        s.y[tid] = obs[tid];
    }
    __syncthreads();
    if (wid == 0) ldqp = warp_gj_solve(s.pc[0], s.t2, s.t3, lane);
    __syncthreads();
    s.Hpc[0][tid] = dot_rc(s.Hq, s.pc[0], i, j);
    if (tid < 16) s.innov[tid] = s.y[tid] - mv(s.Hq, s.pm[0], tid) - s.dq[tid];
    __syncthreads();
    s.S[tid] = dot_rt(s.Hpc[0], s.Hq, i, j) + s.Rq[tid];
    __syncthreads();
    if (wid == 0) ldS0 = warp_gj_solve(s.S, s.Hpc[0], s.K, lane);
    __syncthreads();
    s.fcb[0][tid] = s.pc[0][tid] - dot_rc(s.K, s.Hpc[0], i, j);
    s.G[tid] = s.Om0[tid];
    s.Go[tid] = s.Em[tid];
    if (tid < 16) s.fmb[0][tid] = s.pm[0][tid] + mv(s.K, s.innov, tid);
    __syncthreads();

    // ---- prologue: produce iter-1 inputs (parity w=1) ----
    s.M[1][tid] = dot_rc(s.Wq, s.fcb[0], i, j);
    s.WqPC[tid] = dot_rc(s.WH, s.fcb[0], i, j);  // U_1 temp
    if (tid < 16) {
        s.pm[1][tid] = mv(s.Wq, s.fmb[0], tid) + s.bq[tid];
        s.y[tid] = (Tn > 1) ? obs[16 + tid] : 0.f;
    }
    __syncthreads();
    s.pc[1][tid] = dot_rt(s.M[1], s.Wq, i, j) + s.Sq[tid];
    s.S[tid] = dot_rt(s.WqPC, s.WH, i, j) + s.C2[tid];
    s.Hpc[1][tid] = dot_rt(s.WqPC, s.Wq, i, j) + s.C1[tid];
    if (tid < 16) s.innov[tid] = s.y[tid] - mv(s.WH, s.fmb[0], tid) - s.cq2[tid];
    __syncthreads();

    // thread-0 setup scalars
    double set_acc = 0.0, K0d = 0.0, ldfc0 = 0.0, LDSqd = 0.0, LDRqd = 0.0;
    if (tid == 0) {
        set_acc = -0.5 * (16.0 * LOG2PI + (double)LDpr)
                - 0.5 * (16.0 * LOG2PI + (double)LDe);
        K0d = -8.0 * LOG2PI - 0.5 * (double)LDe - 0.5 * (double)LDp + 8.0;
        ldfc0 = (double)ldqp + (double)LDRq - (double)ldS0;  // logdet(fc_0)
        LDSqd = (double)LDSq;
        LDRqd = (double)LDRq;
    }

    double accel = 0.0, d0 = 0.0;
    float lastld = 0.f;

    // ================= split pipeline =================
    if (tid < 128) {
        // -------- group A: Kalman recursion --------
        const int l = tid;
        const int ia0 = l >> 4, ia1 = ia0 + 8, ja = l & 15;
        const int e0 = ia0 * 16 + ja, e1 = ia1 * 16 + ja;
        for (int t = 1; t < Tn; t++) {
            const int w = t & 1, r = w ^ 1;
            // GJ stage: warp0 solves S K^T = Hpc; warps1-3 precompute
            if (wid == 0) {
                float ld = warp_gj_solve(s.S, s.Hpc[w], s.K, lane);
                d0 += (double)ld;  // sum lds
                lastld = ld;       // lds_N
            } else {
                const int m = tid - 32;  // 0..95
                for (int e = m; e < 256; e += 96) {
                    int ei = e >> 4, ej = e & 15;
                    s.WqPC[e] = dot_rc(s.Wq, s.pc[w], ei, ej);
                    s.WHPC[e] = dot_rc(s.WH, s.pc[w], ei, ej);
                }
                BAR4();
                for (int e = m; e < 256; e += 96) {
                    int ei = e >> 4, ej = e & 15;
                    s.Pqq[e] = dot_rt(s.WqPC, s.Wq, ei, ej);
                    s.Phh[e] = dot_rt(s.WHPC, s.WH, ei, ej);
                    s.Phq[e] = dot_rt(s.WHPC, s.Wq, ei, ej);
                    s.HW[e] = dot_rt(s.Hpc[w], s.Wq, ei, ej);
                    s.HH[e] = dot_rt(s.Hpc[w], s.WH, ei, ej);
                }
            }
            BARA();
            // P1: WqK, WHK, fc_t, fm_t
            s.WqK[e0] = dot_rc(s.Wq, s.K, ia0, ja);
            s.WqK[e1] = dot_rc(s.Wq, s.K, ia1, ja);
            s.WHK[e0] = dot_rc(s.WH, s.K, ia0, ja);
            s.WHK[e1] = dot_rc(s.WH, s.K, ia1, ja);
            s.fcb[w][e0] = s.pc[w][e0] - dot_rc(s.K, s.Hpc[w], ia0, ja);
            s.fcb[w][e1] = s.pc[w][e1] - dot_rc(s.K, s.Hpc[w], ia1, ja);
            if (l < 16) s.fmb[w][l] = s.pm[w][l] + mv(s.K, s.innov, l);
            BARA();
            // P2: next-iteration inputs (parity r)
            s.M[r][e0] = s.WqPC[e0] - dot_rc(s.WqK, s.Hpc[w], ia0, ja);
            s.M[r][e1] = s.WqPC[e1] - dot_rc(s.WqK, s.Hpc[w], ia1, ja);
            s.pc[r][e0] = s.Pqq[e0] - dot_rc(s.WqK, s.HW, ia0, ja) + s.Sq[e0];
            s.pc[r][e1] = s.Pqq[e1] - dot_rc(s.WqK, s.HW, ia1, ja) + s.Sq[e1];
            s.S[e0] = s.Phh[e0] - dot_rc(s.WHK, s.HH, ia0, ja) + s.C2[e0];
            s.S[e1] = s.Phh[e1] - dot_rc(s.WHK, s.HH, ia1, ja) + s.C2[e1];
            s.Hpc[r][e0] = s.Phq[e0] - dot_rc(s.WHK, s.HW, ia0, ja) + s.C1[e0];
            s.Hpc[r][e1] = s.Phq[e1] - dot_rc(s.WHK, s.HW, ia1, ja) + s.C1[e1];
            if (l < 16 && t + 1 < Tn) {
                s.pm[r][l] = mv(s.Wq, s.fmb[w], l) + s.bq[l];
                float yy = obs[(t + 1) * 16 + l];
                s.y[l] = yy;
                s.innov[l] = yy - mv(s.WH, s.fmb[w], l) - s.cq2[l];
            }
            BAR0();
        }
    } else {
        // -------- group B: side chain --------
        const int l = tid - 128;
        const int ib0 = l >> 4, ib1 = ib0 + 8, jb = l & 15;
        const int e0 = ib0 * 16 + jb, e1 = ib1 * 16 + jb;
        for (int t = 1; t < Tn; t++) {
            const int w = t & 1, r = w ^ 1;
            // stage D: warp5 GJ(pc,M); warps 4,6,7 deferred step t-1 work
            if (wid == 5) {
                float ld = warp_gj_solve(s.pc[w], s.M[w], s.bA[w], lane);
                d0 += (double)ld;  // sum ldp
                lastld = ld;       // ldp_N
            } else {
                if (t > 1) {
                    const int m = (l < 32) ? l : (l - 32);  // 0..95 over warps 4,6,7
                    for (int e = m; e < 256; e += 96) {
                        int ei = e >> 4, ej = e & 15;
                        s.OmpA[e] = dot_rc(s.Om_p, s.t1, ei, ej);
                    }
                    BAR3();
                    for (int e = m; e < 256; e += 96) {
                        int ei = e >> 4, ej = e & 15;
                        accel += (double)((s.G[e] + s.Go[e] - 0.5f * s.Fm[e]) * s.bcov[e]);
                        float g = dot_tc(s.bA[r], s.t2, ei, ej) + dot_tc(s.t1, s.OmpA, ei, ej);
                        float go = dot_tc(s.bA[r], s.t3, ei, ej) + s.Em[e];
                        s.G[e] = g;
                        s.Go[e] = go;
                    }
                }
            }
            BARB();
            // B2: t1, t2, t3, bcov, stores
            s.t1[e0] = dot_rc(s.Wp, s.bA[w], ib0, jb) - ((ib0 == jb) ? 1.f : 0.f);
            s.t1[e1] = dot_rc(s.Wp, s.bA[w], ib1, jb) - ((ib1 == jb) ? 1.f : 0.f);
            s.t2[e0] = dot_rc(s.G, s.bA[w], ib0, jb);
            s.t2[e1] = dot_rc(s.G, s.bA[w], ib1, jb);
            s.t3[e0] = dot_rc(s.Go, s.bA[w], ib0, jb);
            s.t3[e1] = dot_rc(s.Go, s.bA[w], ib1, jb);
            s.bcov[e0] = s.fcb[r][e0] - dot_rc(s.bA[w], s.M[w], ib0, jb);
            s.bcov[e1] = s.fcb[r][e1] - dot_rc(s.bA[w], s.M[w], ib1, jb);
            g_P[t][e0] = s.bA[w][e0];
            g_P[t][e1] = s.bA[w][e1];
            if (l < 16) g_ba[t][l] = s.fmb[r][l] - mv(s.bA[w], s.pm[w], l);
            BAR0();
        }
        // flush: accel term for step Tn-1 (G,Go at state through Tn-2; bcov_{Tn-1})
        if (Tn > 1) {
            accel += (double)((s.G[e0] + s.Go[e0] - 0.5f * s.Fm[e0]) * s.bcov[e0])
                   + (double)((s.G[e1] + s.Go[e1] - 0.5f * s.Fm[e1]) * s.bcov[e1]);
        }
    }
    __syncthreads();

    // ---- epilogue ----
    g_OmP[tid] = s.Om_p[tid];
    g_om[tid] = s.om[tid];
    g_Om0[tid] = s.Om0[tid];
    {
        int fp = (Tn - 1) & 1;
        g_fcF[tid] = s.fcb[fp][tid];
        if (tid < 16) g_fmF[tid] = s.fmb[fp][tid];
    }
    double v = accel;
#pragma unroll
    for (int o = 16; o; o >>= 1) v += __shfl_xor_sync(0xffffffffu, v, o);
    if (lane == 0) s.dred[wid] = v;
    if (tid == 160) {
        s.dsc[0] = d0;              // SP = sum ldp_t
        s.dsc[1] = (double)lastld;  // ldp_N
    }
    __syncthreads();
    if (tid == 0) {
        double elem = 0.0;
#pragma unroll
        for (int w = 0; w < 8; w++) elem += s.dred[w];
        double SP = s.dsc[0], ldpN = s.dsc[1];
        double sumS = d0, ldsN = (double)lastld;
        double N = (double)(Tn - 1);
        double sumF = ldfc0 + (SP - ldpN) + (N - 1.0) * LDRqd - (sumS - ldsN);
        double FN = ldpN + LDRqd - ldsN;
        double sc = set_acc
                  + N * (K0d + 0.5 * LDSqd)
                  - 0.5 * SP
                  + 0.5 * sumF
                  + 0.5 * (16.0 * LOG2PI + FN) + 8.0
                  + elem;
        g_part[64] = sc;
    }
}

// ---------------- backward scan kernels ----------------
#define SEG 8
__global__ void __launch_bounds__(256, 1) lgq_scan1(int Tn) {
    const int b = blockIdx.x;
    const int lo = b * SEG;
    int hi = lo + SEG;
    if (hi > Tn) hi = Tn;
    __shared__ float R[256], Rn[256], bA[256];
    __shared__ float u[16], un[16], ba[16];
    const int tid = threadIdx.x;
    const int i = tid >> 4, j = tid & 15;
    R[tid] = (i == j) ? 1.f : 0.f;
    if (tid < 16) u[tid] = 0.f;
    __syncthreads();
    for (int t = hi - 1; t >= lo; t--) {
        g_Lr[t][tid] = R[tid];
        if (tid < 16) g_Lu[t][tid] = u[tid];
        if (t == 0) break;
        bA[tid] = g_P[t][tid];
        if (tid < 16) ba[tid] = g_ba[t][tid];
        __syncthreads();
        Rn[tid] = dot_rc(bA, R, i, j);
        if (tid < 16) un[tid] = ba[tid] + mv(bA, u, tid);
        __syncthreads();
        R[tid] = Rn[tid];
        if (tid < 16) u[tid] = un[tid];
        __syncthreads();
    }
    g_Sr[b][tid] = R[tid];
    if (tid < 16) g_Su[b][tid] = u[tid];
}

__global__ void __launch_bounds__(256, 1) lgq_scan2(int Tn) {
    const int nseg = (Tn + SEG - 1) / SEG;
    __shared__ float Gr[256], Gn[256], Sr[256];
    __shared__ float Gu[16], gn[16], Su[16];
    const int tid = threadIdx.x;
    const int i = tid >> 4, j = tid & 15;
    Gr[tid] = (i == j) ? 1.f : 0.f;
    if (tid < 16) Gu[tid] = 0.f;
    __syncthreads();
    for (int b = nseg - 1; b >= 0; b--) {
        g_Gr[b][tid] = Gr[tid];
        if (tid < 16) g_Gu[b][tid] = Gu[tid];
        if (b == 0) break;
        Sr[tid] = g_Sr[b][tid];
        if (tid < 16) Su[tid] = g_Su[b][tid];
        __syncthreads();
        Gn[tid] = dot_rc(Sr, Gr, i, j);
        if (tid < 16) gn[tid] = mv(Sr, Gu, tid) + Su[tid];
        __syncthreads();
        Gr[tid] = Gn[tid];
        if (tid < 16) Gu[tid] = gn[tid];
        __syncthreads();
    }
}

#define EVT 4
__global__ void __launch_bounds__(256, 1) lgq_scan3(
    const float* obs, const float* p_trans_w, const float* p_trans_b,
    const float* p_emis_w, const float* p_emis_b, const float* p_prior_mean,
    int Tn) {
    const int b = blockIdx.x;
    const int lo = b * EVT;
    int hi = lo + EVT;
    if (hi > Tn) hi = Tn;
    const int seg = lo / SEG;
    __shared__ float OmP[256], omm[256], Om0[256], Wp[256], Wep[256], fc[256], Gr[256];
    __shared__ float Lr[256], bA[256], Rf[256], Ai[256], A[256], Ao[256], AF[256], AoF[256];
    __shared__ float fm[16], Gu[16], Lu[16], bav[16], uf[16], Bv[16], Bo[16];
    __shared__ float cv[16], co[16], y[16], bp[16], ebp[16], ppm[16];
    __shared__ double dred[8];
    const int tid = threadIdx.x;
    const int i = tid >> 4, j = tid & 15;
    const int lane = tid & 31, wid = tid >> 5;

    OmP[tid] = g_OmP[tid];
    omm[tid] = g_om[tid];
    Om0[tid] = g_Om0[tid];
    Wp[tid] = p_trans_w[tid];
    Wep[tid] = p_emis_w[tid];
    fc[tid] = g_fcF[tid];
    Gr[tid] = g_Gr[seg][tid];
    if (tid < 16) {
        fm[tid] = g_fmF[tid];
        Gu[tid] = g_Gu[seg][tid];
        bp[tid] = p_trans_b[tid];
        ebp[tid] = p_emis_b[tid];
        ppm[tid] = p_prior_mean[tid];
    }
    __syncthreads();

    double acc = 0.0;
    for (int t = lo; t < hi; t++) {
        Lr[tid] = g_Lr[t][tid];
        bA[tid] = (t > 0) ? g_P[t][tid] : 0.f;
        if (tid < 16) {
            Lu[tid] = g_Lu[t][tid];
            bav[tid] = (t > 0) ? g_ba[t][tid] : 0.f;
            y[tid] = obs[t * 16 + tid];
        }
        __syncthreads();
        Rf[tid] = dot_rc(Lr, Gr, i, j);
        Ai[tid] = (t > 0) ? (dot_rc(Wp, bA, i, j) - ((i == j) ? 1.f : 0.f))
                          : ((i == j) ? 1.f : 0.f);
        if (tid < 16) {
            uf[tid] = mv(Lr, Gu, tid) + Lu[tid];
            Bv[tid] = (t > 0) ? (mv(Wp, bav, tid) + bp[tid]) : (-ppm[tid]);
        }
        __syncthreads();
        A[tid] = dot_rc(Ai, Rf, i, j);
        Ao[tid] = dot_rc(Wep, Rf, i, j);
        if (tid < 16) {
            Bv[tid] += mv(Ai, uf, tid);
            Bo[tid] = ebp[tid] - y[tid] + mv(Wep, uf, tid);
        }
        __syncthreads();
        AF[tid] = dot_rc(A, fc, i, j);
        AoF[tid] = dot_rc(Ao, fc, i, j);
        if (tid < 16) {
            cv[tid] = mv(A, fm, tid) + Bv[tid];
            co[tid] = mv(Ao, fm, tid) + Bo[tid];
        }
        __syncthreads();
        {
            const float* Om = (t == 0) ? Om0 : OmP;
            float val = Om[tid] * (dot_rc(AF, A, i, j) + cv[i] * cv[j])
                      + omm[tid] * (dot_rc(AoF, Ao, i, j) + co[i] * co[j]);
            acc += (double)val;
        }
        __syncthreads();
    }

    double v = acc;
#pragma unroll
    for (int o = 16; o; o >>= 1) v += __shfl_xor_sync(0xffffffffu, v, o);
    if (lane == 0) dred[wid] = v;
    __syncthreads();
    if (tid == 0) {
        double tot = 0.0;
#pragma unroll
        for (int w = 0; w < 8; w++) tot += dred[w];
        g_part[b] = tot;
    }
}

__global__ void lgq_fin(float* out, int Tn) {
    if (threadIdx.x == 0) {
        const int nblk = (Tn + EVT - 1) / EVT;
        double tot = g_part[64];
        for (int b = 0; b < nblk; b++) tot += g_part[b];
        out[0] = (float)tot;
    }
}

extern "C" void kernel_launch(void* const* d_in, const int* in_sizes, int n_in,
                              void* d_out, int out_size) {
    int Tn = in_sizes[0] / 16;
    if (Tn > TMAX) Tn = TMAX;
    const int nseg = (Tn + SEG - 1) / SEG;
    const int nblk = (Tn + EVT - 1) / EVT;
    lgq_fwd<<<1, 256>>>(
        (const float*)d_in[0], (const float*)d_in[1], (const float*)d_in[2],
        (const float*)d_in[3], (const float*)d_in[4], (const float*)d_in[5],
        (const float*)d_in[6], (const float*)d_in[7], (const float*)d_in[8],
        (const float*)d_in[9], (const float*)d_in[10], (const float*)d_in[11],
        (const float*)d_in[12], (const float*)d_in[13], (const float*)d_in[14],
        (const float*)d_in[15], (const float*)d_in[16], Tn);
    lgq_scan1<<<nseg, 256>>>(Tn);
    lgq_scan2<<<1, 256>>>(Tn);
    lgq_scan3<<<nblk, 256>>>(
        (const float*)d_in[0], (const float*)d_in[3], (const float*)d_in[4],
        (const float*)d_in[6], (const float*)d_in[7], (const float*)d_in[1], Tn);
    lgq_fin<<<1, 32>>>((float*)d_out, Tn);
}

// round 7
// speedup vs baseline: 1.9458x; 1.9458x over previous
#include <cuda_runtime.h>
#include <math.h>

#define TMAX 256
#define LOG2PI 1.8378770664093453

// ---------------- device scratch ----------------
__device__ float g_P[TMAX][256];
__device__ float g_ba[TMAX][16];
__device__ float g_Lr[TMAX][256];
__device__ float g_Lu[TMAX][16];
__device__ float g_Sr[32][256];
__device__ float g_Su[32][16];
__device__ float g_Gr[32][256];
__device__ float g_Gu[32][16];
__device__ float g_OmP[256], g_om[256], g_Om0[256];
__device__ float g_fcF[256], g_fmF[16];
__device__ double g_part[65];

#define BARH() asm volatile("bar.sync 5, 160;" ::: "memory")

// ---------------- dot helpers ----------------
__device__ __forceinline__ float dot_rc(const float* A, const float* B, int i, int j) {
    float s = 0.f;
#pragma unroll
    for (int k = 0; k < 16; k++) s = fmaf(A[i * 16 + k], B[k * 16 + j], s);
    return s;
}
__device__ __forceinline__ float dot_tc(const float* A, const float* B, int i, int j) { // A^T B
    float s = 0.f;
#pragma unroll
    for (int k = 0; k < 16; k++) s = fmaf(A[k * 16 + i], B[k * 16 + j], s);
    return s;
}
__device__ __forceinline__ float dot_rt(const float* A, const float* B, int i, int j) { // A B^T
    float s = 0.f;
#pragma unroll
    for (int k = 0; k < 16; k++) s = fmaf(A[i * 16 + k], B[j * 16 + k], s);
    return s;
}
__device__ __forceinline__ float dot_rowreg_col(const float* row, const float* B, int j) {
    float s = 0.f;
#pragma unroll
    for (int k = 0; k < 16; k++) s = fmaf(row[k], B[k * 16 + j], s);
    return s;
}
__device__ __forceinline__ float dot_row_rowreg(const float* A, const float* row, int i) {
    float s = 0.f;
#pragma unroll
    for (int k = 0; k < 16; k++) s = fmaf(A[i * 16 + k], row[k], s);
    return s;
}
__device__ __forceinline__ float mv(const float* M, const float* v, int r) {
    float s = 0.f;
#pragma unroll
    for (int k = 0; k < 16; k++) s = fmaf(M[r * 16 + k], v[k], s);
    return s;
}

// Single-warp register-resident Gauss-Jordan solve: A (16x16 SPD) X = B.
// Writes X^T (row-major) to Xt. Returns logdet(A) on all lanes.
__device__ __forceinline__ float warp_gj_solve(const float* Am, const float* Bm,
                                               float* Xt, int lane) {
    float a[16];
    {
        const float* src = (lane < 16) ? (Am + lane) : (Bm + lane - 16);
#pragma unroll
        for (int r = 0; r < 16; r++) a[r] = src[r * 16];
    }
    float mypiv = 1.f;
#pragma unroll
    for (int p = 0; p < 16; p++) {
        float f[16];
#pragma unroll
        for (int r = 0; r < 16; r++) f[r] = __shfl_sync(0xffffffffu, a[r], p);
        float x = f[p];
        if (lane == p) mypiv = x;
        float r0;
        asm("rcp.approx.f32 %0, %1;" : "=f"(r0) : "f"(x));
        float pivinv = r0 * (2.0f - x * r0);
        a[p] *= pivinv;
#pragma unroll
        for (int r = 0; r < 16; r++)
            if (r != p) a[r] = fmaf(-f[r], a[p], a[r]);
    }
    float lg = __logf(mypiv);
#pragma unroll
    for (int o = 16; o; o >>= 1) lg += __shfl_xor_sync(0xffffffffu, lg, o);
    if (lane >= 16) {
        float4* dst = reinterpret_cast<float4*>(Xt + (lane - 16) * 16);
        dst[0] = make_float4(a[0], a[1], a[2], a[3]);
        dst[1] = make_float4(a[4], a[5], a[6], a[7]);
        dst[2] = make_float4(a[8], a[9], a[10], a[11]);
        dst[3] = make_float4(a[12], a[13], a[14], a[15]);
    }
    return lg;
}

// ---------------- forward kernel ----------------
struct SMF {
    float Wq[256], Sq[256], Hq[256], Rq[256], Wp[256], Wep[256];
    float WH[256], C1[256], C2[256];
    float Om_p[256], om[256], Om0[256], Em[256], Fm[256];
    float fcb[2][256], M[2][256], pc[2][256], Hpc[2][256], bA[2][256];
    float S[256], K[256], U[256];
    float t1[256], t2[256], t3[256], OmpA[256], G[256], Go[256], bcov[256];
    float bq[16], dq[16], bp[16], ebp[16], ppm[16];
    float fmb[2][16], pm[2][16], innov[16], y[16];
    double dred[8], dsc[2];
};

__global__ void __launch_bounds__(256, 1) lgq_fwd(
    const float* obs, const float* p_prior_mean, const float* p_prior_cov,
    const float* p_trans_w, const float* p_trans_b, const float* p_trans_cov,
    const float* p_emis_w, const float* p_emis_b, const float* p_emis_cov,
    const float* q_prior_mean, const float* q_prior_cov, const float* q_trans_w,
    const float* q_trans_b, const float* q_trans_cov, const float* q_emis_w,
    const float* q_emis_b, const float* q_emis_cov, int Tn) {
    __shared__ SMF s;
    const int tid = threadIdx.x;
    const int i = tid >> 4, j = tid & 15;
    const int lane = tid & 31, wid = tid >> 5;

    // load constants
    s.Wq[tid] = q_trans_w[tid];
    s.Sq[tid] = q_trans_cov[tid];
    s.Hq[tid] = q_emis_w[tid];
    s.Rq[tid] = q_emis_cov[tid];
    s.Wp[tid] = p_trans_w[tid];
    s.Wep[tid] = p_emis_w[tid];
    if (tid < 16) {
        s.bq[tid] = q_trans_b[tid];
        s.dq[tid] = q_emis_b[tid];
        s.bp[tid] = p_trans_b[tid];
        s.ebp[tid] = p_emis_b[tid];
        s.ppm[tid] = p_prior_mean[tid];
    }
    __syncthreads();

    // derived constants
    s.WH[tid] = dot_rc(s.Hq, s.Wq, i, j);
    s.C1[tid] = dot_rc(s.Hq, s.Sq, i, j);

    // cached register rows (for stages st2/st3)
    float wqi[16], whi_[16], wqj[16], whj[16];

    // ---- setup: constant inverses / logdets ----
    float LDp = 0.f, LDe = 0.f, LDpr = 0.f, LDSq = 0.f, LDRq = 0.f, ldqp = 0.f, ldS0 = 0.f;
    s.t2[tid] = (i == j) ? 1.f : 0.f;  // identity RHS
    s.S[tid] = p_trans_cov[tid];
    __syncthreads();
    s.C2[tid] = dot_rt(s.C1, s.Hq, i, j) + s.Rq[tid];
    if (wid == 0) LDp = warp_gj_solve(s.S, s.t2, s.K, lane);
    __syncthreads();
    s.Om_p[tid] = -0.5f * s.K[tid];
    s.t3[tid] = dot_rc(s.K, s.Wp, i, j);
    __syncthreads();
    s.Fm[tid] = dot_tc(s.Wp, s.t3, i, j);
    s.S[tid] = p_emis_cov[tid];
    __syncthreads();
    if (wid == 0) LDe = warp_gj_solve(s.S, s.t2, s.K, lane);
    __syncthreads();
    s.om[tid] = -0.5f * s.K[tid];
    s.S[tid] = p_prior_cov[tid];
    __syncthreads();
    s.t3[tid] = dot_rc(s.om, s.Wep, i, j);
    if (wid == 0) LDpr = warp_gj_solve(s.S, s.t2, s.K, lane);
    __syncthreads();
    s.Em[tid] = dot_tc(s.Wep, s.t3, i, j);
    s.Om0[tid] = -0.5f * s.K[tid];
    s.S[tid] = q_trans_cov[tid];
    __syncthreads();
    if (wid == 0) LDSq = warp_gj_solve(s.S, s.t2, s.t3, lane);
    __syncthreads();
    s.S[tid] = q_emis_cov[tid];
    __syncthreads();
    if (wid == 0) LDRq = warp_gj_solve(s.S, s.t2, s.t3, lane);
    __syncthreads();

    // ---- t=0 Kalman update ----
    s.pc[0][tid] = q_prior_cov[tid];
    if (tid < 16) {
        s.pm[0][tid] = q_prior_mean[tid];
        s.y[tid] = obs[tid];
    }
    __syncthreads();
    if (wid == 0) ldqp = warp_gj_solve(s.pc[0], s.t2, s.t3, lane);
    __syncthreads();
    s.Hpc[0][tid] = dot_rc(s.Hq, s.pc[0], i, j);
    if (tid < 16) s.innov[tid] = s.y[tid] - mv(s.Hq, s.pm[0], tid) - s.dq[tid];
    __syncthreads();
    s.S[tid] = dot_rt(s.Hpc[0], s.Hq, i, j) + s.Rq[tid];
    __syncthreads();
    if (wid == 0) ldS0 = warp_gj_solve(s.S, s.Hpc[0], s.K, lane);
    __syncthreads();
    s.fcb[0][tid] = s.pc[0][tid] - dot_rc(s.K, s.Hpc[0], i, j);
    s.G[tid] = s.Om0[tid];
    s.Go[tid] = s.Em[tid];
    if (tid < 16) s.fmb[0][tid] = s.pm[0][tid] + mv(s.K, s.innov, tid);
    __syncthreads();

    // cache rows now that WH is final
#pragma unroll
    for (int k = 0; k < 16; k++) {
        wqi[k] = s.Wq[i * 16 + k];
        whi_[k] = s.WH[i * 16 + k];
        wqj[k] = s.Wq[j * 16 + k];
        whj[k] = s.WH[j * 16 + k];
    }

    // ---- prologue: produce iter-1 inputs (parity w=1) ----
    s.M[1][tid] = dot_rowreg_col(wqi, s.fcb[0], j);
    s.U[tid] = dot_rowreg_col(whi_, s.fcb[0], j);
    if (tid < 16) {
        s.pm[1][tid] = mv(s.Wq, s.fmb[0], tid) + s.bq[tid];
        s.y[tid] = (Tn > 1) ? obs[16 + tid] : 0.f;
    }
    __syncthreads();
    s.pc[1][tid] = dot_row_rowreg(s.M[1], wqj, i) + s.Sq[tid];
    s.S[tid] = dot_row_rowreg(s.U, whj, i) + s.C2[tid];
    s.Hpc[1][tid] = dot_row_rowreg(s.U, wqj, i) + s.C1[tid];
    if (tid < 16) s.innov[tid] = s.y[tid] - mv(s.Hq, s.pm[1], tid) - s.dq[tid];
    __syncthreads();

    // thread-0 setup scalars
    double set_acc = 0.0, K0d = 0.0, ldfc0 = 0.0, LDSqd = 0.0, LDRqd = 0.0;
    if (tid == 0) {
        set_acc = -0.5 * (16.0 * LOG2PI + (double)LDpr)
                - 0.5 * (16.0 * LOG2PI + (double)LDe);
        K0d = -8.0 * LOG2PI - 0.5 * (double)LDe - 0.5 * (double)LDp + 8.0;
        ldfc0 = (double)ldqp + (double)LDRq - (double)ldS0;  // logdet(fc_0)
        LDSqd = (double)LDSq;
        LDRqd = (double)LDRq;
    }

    double accel = 0.0, d0 = 0.0;
    float lastld = 0.f;

    // ================= unified pipeline =================
    for (int t = 1; t < Tn; t++) {
        const int w = t & 1, r = w ^ 1;
        // --- GJ phase: warp0 GJ(S); warp5 GJ(pc); helpers deferred Gram(t-1); warp4 idle ---
        if (wid == 0) {
            float ld = warp_gj_solve(s.S, s.Hpc[w], s.K, lane);
            d0 += (double)ld;  // sum lds
            lastld = ld;       // lds_N
        } else if (wid == 5) {
            float ld = warp_gj_solve(s.pc[w], s.M[w], s.bA[w], lane);
            d0 += (double)ld;  // sum ldp
            lastld = ld;       // ldp_N
        } else if (wid != 4) {
            if (t >= 2) {
                const int h = (wid < 4) ? (tid - 32) : (tid - 96);  // 0..159
                for (int e = h; e < 256; e += 160) {
                    int ei = e >> 4, ej = e & 15;
                    s.OmpA[e] = dot_rc(s.Om_p, s.t1, ei, ej);
                }
                BARH();
                for (int e = h; e < 256; e += 160) {
                    int ei = e >> 4, ej = e & 15;
                    accel += (double)((s.G[e] + s.Go[e] - 0.5f * s.Fm[e]) * s.bcov[e]);
                    float g = dot_tc(s.bA[r], s.t2, ei, ej) + dot_tc(s.t1, s.OmpA, ei, ej);
                    float go = dot_tc(s.bA[r], s.t3, ei, ej) + s.Em[e];
                    s.G[e] = g;
                    s.Go[e] = go;
                }
            }
        }
        __syncthreads();
        // --- st1: fc, fm, t1, t2, t3, bcov, stores ---
        s.fcb[w][tid] = s.pc[w][tid] - dot_rc(s.K, s.Hpc[w], i, j);
        s.t1[tid] = dot_rc(s.Wp, s.bA[w], i, j) - ((i == j) ? 1.f : 0.f);
        s.t2[tid] = dot_rc(s.G, s.bA[w], i, j);
        s.t3[tid] = dot_rc(s.Go, s.bA[w], i, j);
        s.bcov[tid] = s.fcb[r][tid] - dot_rc(s.bA[w], s.M[w], i, j);
        g_P[t][tid] = s.bA[w][tid];
        if (tid < 16) {
            s.fmb[w][tid] = s.pm[w][tid] + mv(s.K, s.innov, tid);
            g_ba[t][tid] = s.fmb[r][tid] - mv(s.bA[w], s.pm[w], tid);
        }
        __syncthreads();
        // --- st2: M', U', pm', y ---
        s.M[r][tid] = dot_rowreg_col(wqi, s.fcb[w], j);
        s.U[tid] = dot_rowreg_col(whi_, s.fcb[w], j);
        if (tid < 16 && t + 1 < Tn) {
            s.pm[r][tid] = mv(s.Wq, s.fmb[w], tid) + s.bq[tid];
            s.y[tid] = obs[(t + 1) * 16 + tid];
        }
        __syncthreads();
        // --- st3: pc', S', Hpc', innov' ---
        s.pc[r][tid] = dot_row_rowreg(s.M[r], wqj, i) + s.Sq[tid];
        s.S[tid] = dot_row_rowreg(s.U, whj, i) + s.C2[tid];
        s.Hpc[r][tid] = dot_row_rowreg(s.U, wqj, i) + s.C1[tid];
        if (tid < 16 && t + 1 < Tn)
            s.innov[tid] = s.y[tid] - mv(s.Hq, s.pm[r], tid) - s.dq[tid];
        __syncthreads();
    }

    // flush: accel term for step Tn-1 (G,Go through Tn-2; bcov from step Tn-1)
    if (Tn > 1)
        accel += (double)((s.G[tid] + s.Go[tid] - 0.5f * s.Fm[tid]) * s.bcov[tid]);

    // ---- epilogue ----
    g_OmP[tid] = s.Om_p[tid];
    g_om[tid] = s.om[tid];
    g_Om0[tid] = s.Om0[tid];
    {
        int fp = (Tn - 1) & 1;
        g_fcF[tid] = s.fcb[fp][tid];
        if (tid < 16) g_fmF[tid] = s.fmb[fp][tid];
    }
    double v = accel;
#pragma unroll
    for (int o = 16; o; o >>= 1) v += __shfl_xor_sync(0xffffffffu, v, o);
    if (lane == 0) s.dred[wid] = v;
    if (tid == 160) {
        s.dsc[0] = d0;              // SP = sum ldp_t
        s.dsc[1] = (double)lastld;  // ldp_N
    }
    __syncthreads();
    if (tid == 0) {
        double elem = 0.0;
#pragma unroll
        for (int w = 0; w < 8; w++) elem += s.dred[w];
        double SP = s.dsc[0], ldpN = s.dsc[1];
        double sumS = d0, ldsN = (double)lastld;
        double N = (double)(Tn - 1);
        double sumF = ldfc0 + (SP - ldpN) + (N - 1.0) * LDRqd - (sumS - ldsN);
        double FN = ldpN + LDRqd - ldsN;
        double sc = set_acc
                  + N * (K0d + 0.5 * LDSqd)
                  - 0.5 * SP
                  + 0.5 * sumF
                  + 0.5 * (16.0 * LOG2PI + FN) + 8.0
                  + elem;
        g_part[64] = sc;
    }
}

// ---------------- backward scan kernels ----------------
#define SEG 8
__global__ void __launch_bounds__(256, 1) lgq_scan1(int Tn) {
    const int b = blockIdx.x;
    const int lo = b * SEG;
    int hi = lo + SEG;
    if (hi > Tn) hi = Tn;
    __shared__ float R[256], Rn[256], bA[256];
    __shared__ float u[16], un[16], ba[16];
    const int tid = threadIdx.x;
    const int i = tid >> 4, j = tid & 15;
    R[tid] = (i == j) ? 1.f : 0.f;
    if (tid < 16) u[tid] = 0.f;
    __syncthreads();
    for (int t = hi - 1; t >= lo; t--) {
        g_Lr[t][tid] = R[tid];
        if (tid < 16) g_Lu[t][tid] = u[tid];
        if (t == 0) break;
        bA[tid] = g_P[t][tid];
        if (tid < 16) ba[tid] = g_ba[t][tid];
        __syncthreads();
        Rn[tid] = dot_rc(bA, R, i, j);
        if (tid < 16) un[tid] = ba[tid] + mv(bA, u, tid);
        __syncthreads();
        R[tid] = Rn[tid];
        if (tid < 16) u[tid] = un[tid];
        __syncthreads();
    }
    g_Sr[b][tid] = R[tid];
    if (tid < 16) g_Su[b][tid] = u[tid];
}

__global__ void __launch_bounds__(256, 1) lgq_scan2(int Tn) {
    const int nseg = (Tn + SEG - 1) / SEG;
    __shared__ float Gr[256], Gn[256], Sr[256];
    __shared__ float Gu[16], gn[16], Su[16];
    const int tid = threadIdx.x;
    const int i = tid >> 4, j = tid & 15;
    Gr[tid] = (i == j) ? 1.f : 0.f;
    if (tid < 16) Gu[tid] = 0.f;
    __syncthreads();
    for (int b = nseg - 1; b >= 0; b--) {
        g_Gr[b][tid] = Gr[tid];
        if (tid < 16) g_Gu[b][tid] = Gu[tid];
        if (b == 0) break;
        Sr[tid] = g_Sr[b][tid];
        if (tid < 16) Su[tid] = g_Su[b][tid];
        __syncthreads();
        Gn[tid] = dot_rc(Sr, Gr, i, j);
        if (tid < 16) gn[tid] = mv(Sr, Gu, tid) + Su[tid];
        __syncthreads();
        Gr[tid] = Gn[tid];
        if (tid < 16) Gu[tid] = gn[tid];
        __syncthreads();
    }
}

#define EVT 4
__global__ void __launch_bounds__(256, 1) lgq_scan3(
    const float* obs, const float* p_trans_w, const float* p_trans_b,
    const float* p_emis_w, const float* p_emis_b, const float* p_prior_mean,
    int Tn) {
    const int b = blockIdx.x;
    const int lo = b * EVT;
    int hi = lo + EVT;
    if (hi > Tn) hi = Tn;
    const int seg = lo / SEG;
    __shared__ float OmP[256], omm[256], Om0[256], Wp[256], Wep[256], fc[256], Gr[256];
    __shared__ float Lr[256], bA[256], Rf[256], Ai[256], A[256], Ao[256], AF[256], AoF[256];
    __shared__ float fm[16], Gu[16], Lu[16], bav[16], uf[16], Bv[16], Bo[16];
    __shared__ float cv[16], co[16], y[16], bp[16], ebp[16], ppm[16];
    __shared__ double dred[8];
    const int tid = threadIdx.x;
    const int i = tid >> 4, j = tid & 15;
    const int lane = tid & 31, wid = tid >> 5;

    OmP[tid] = g_OmP[tid];
    omm[tid] = g_om[tid];
    Om0[tid] = g_Om0[tid];
    Wp[tid] = p_trans_w[tid];
    Wep[tid] = p_emis_w[tid];
    fc[tid] = g_fcF[tid];
    Gr[tid] = g_Gr[seg][tid];
    if (tid < 16) {
        fm[tid] = g_fmF[tid];
        Gu[tid] = g_Gu[seg][tid];
        bp[tid] = p_trans_b[tid];
        ebp[tid] = p_emis_b[tid];
        ppm[tid] = p_prior_mean[tid];
    }
    __syncthreads();

    double acc = 0.0;
    for (int t = lo; t < hi; t++) {
        Lr[tid] = g_Lr[t][tid];
        bA[tid] = (t > 0) ? g_P[t][tid] : 0.f;
        if (tid < 16) {
            Lu[tid] = g_Lu[t][tid];
            bav[tid] = (t > 0) ? g_ba[t][tid] : 0.f;
            y[tid] = obs[t * 16 + tid];
        }
        __syncthreads();
        Rf[tid] = dot_rc(Lr, Gr, i, j);
        Ai[tid] = (t > 0) ? (dot_rc(Wp, bA, i, j) - ((i == j) ? 1.f : 0.f))
                          : ((i == j) ? 1.f : 0.f);
        if (tid < 16) {
            uf[tid] = mv(Lr, Gu, tid) + Lu[tid];
            Bv[tid] = (t > 0) ? (mv(Wp, bav, tid) + bp[tid]) : (-ppm[tid]);
        }
        __syncthreads();
        A[tid] = dot_rc(Ai, Rf, i, j);
        Ao[tid] = dot_rc(Wep, Rf, i, j);
        if (tid < 16) {
            Bv[tid] += mv(Ai, uf, tid);
            Bo[tid] = ebp[tid] - y[tid] + mv(Wep, uf, tid);
        }
        __syncthreads();
        AF[tid] = dot_rc(A, fc, i, j);
        AoF[tid] = dot_rc(Ao, fc, i, j);
        if (tid < 16) {
            cv[tid] = mv(A, fm, tid) + Bv[tid];
            co[tid] = mv(Ao, fm, tid) + Bo[tid];
        }
        __syncthreads();
        {
            const float* Om = (t == 0) ? Om0 : OmP;
            float val = Om[tid] * (dot_rc(AF, A, i, j) + cv[i] * cv[j])
                      + omm[tid] * (dot_rc(AoF, Ao, i, j) + co[i] * co[j]);
            acc += (double)val;
        }
        __syncthreads();
    }

    double v = acc;
#pragma unroll
    for (int o = 16; o; o >>= 1) v += __shfl_xor_sync(0xffffffffu, v, o);
    if (lane == 0) dred[wid] = v;
    __syncthreads();
    if (tid == 0) {
        double tot = 0.0;
#pragma unroll
        for (int w = 0; w < 8; w++) tot += dred[w];
        g_part[b] = tot;
    }
}

__global__ void lgq_fin(float* out, int Tn) {
    if (threadIdx.x == 0) {
        const int nblk = (Tn + EVT - 1) / EVT;
        double tot = g_part[64];
        for (int b = 0; b < nblk; b++) tot += g_part[b];
        out[0] = (float)tot;
    }
}

extern "C" void kernel_launch(void* const* d_in, const int* in_sizes, int n_in,
                              void* d_out, int out_size) {
    int Tn = in_sizes[0] / 16;
    if (Tn > TMAX) Tn = TMAX;
    const int nseg = (Tn + SEG - 1) / SEG;
    const int nblk = (Tn + EVT - 1) / EVT;
    lgq_fwd<<<1, 256>>>(
        (const float*)d_in[0], (const float*)d_in[1], (const float*)d_in[2],
        (const float*)d_in[3], (const float*)d_in[4], (const float*)d_in[5],
        (const float*)d_in[6], (const float*)d_in[7], (const float*)d_in[8],
        (const float*)d_in[9], (const float*)d_in[10], (const float*)d_in[11],
        (const float*)d_in[12], (const float*)d_in[13], (const float*)d_in[14],
        (const float*)d_in[15], (const float*)d_in[16], Tn);
    lgq_scan1<<<nseg, 256>>>(Tn);
    lgq_scan2<<<1, 256>>>(Tn);
    lgq_scan3<<<nblk, 256>>>(
        (const float*)d_in[0], (const float*)d_in[3], (const float*)d_in[4],
        (const float*)d_in[6], (const float*)d_in[7], (const float*)d_in[1], Tn);
    lgq_fin<<<1, 32>>>((float*)d_out, Tn);
}